// round 11
// baseline (speedup 1.0000x reference)
#include <cuda_runtime.h>
#include <cuda_bf16.h>
#include <cstdint>

// ---------------------------------------------------------------------------
// C2fDA via legacy HMMA (mma.sync m16n8k16 bf16), cp.async pipelined +
// ldmatrix fragments. Split-3 hi/lo bf16, fp32 accum (err ~1e-5).
// B=8, C1=512, C=256, D=256, NH=8, NP=4, NL=1, H=W=64, L=4096
// ---------------------------------------------------------------------------

#define NB 8
#define HWN 4096

// ---------------- scratch (allocation-guard-safe) --------------------------
__device__ uint32_t g_xp_h [(size_t)NB*4096*256];
__device__ uint32_t g_xp_l [(size_t)NB*4096*256];
__device__ uint32_t g_catp_h[(size_t)NB*4096*640];   // [a|b|b1|b2|attn] pairs
__device__ uint32_t g_catp_l[(size_t)NB*4096*640];
__device__ uint32_t g_s0p_h[(size_t)NB*4096*128];
__device__ uint32_t g_s0p_l[(size_t)NB*4096*128];
__device__ uint32_t g_smpp_h[(size_t)NB*4096*128];
__device__ uint32_t g_smpp_l[(size_t)NB*4096*128];
__device__ float    g_pj   [(size_t)NB*4096*384];    // [val 256 | off 64 | aw 32 | pad 32]
__device__ uint32_t g_wcv1_h[512*256],  g_wcv1_l[512*256];
__device__ uint32_t g_wcv2_h[512*640],  g_wcv2_l[512*640];
__device__ uint32_t g_wpj_h [384*128],  g_wpj_l [384*128];
__device__ uint32_t g_wop_h [256*128],  g_wop_l [256*128];
__device__ uint32_t g_wc_h  [4*256*1152], g_wc_l[4*256*1152];
__device__ float    g_biasc [384];

__device__ __forceinline__ float silu_f(float x) { return x / (1.f + __expf(-x)); }

__device__ __forceinline__ void hilo16(float v, unsigned short& h, unsigned short& l) {
    __nv_bfloat16 hb = __float2bfloat16(v);
    float res = v - __bfloat162float(hb);
    __nv_bfloat16 lb = __float2bfloat16(res);
    h = __bfloat16_as_ushort(hb); l = __bfloat16_as_ushort(lb);
}
__device__ __forceinline__ void pack2(float v0, float v1, uint32_t& hp, uint32_t& lp) {
    unsigned short h0, l0, h1, l1;
    hilo16(v0, h0, l0); hilo16(v1, h1, l1);
    hp = ((uint32_t)h1 << 16) | h0;
    lp = ((uint32_t)l1 << 16) | l0;
}

__device__ __forceinline__ void mma16816(float* d, const uint32_t* a, const uint32_t* b) {
    asm volatile(
        "mma.sync.aligned.m16n8k16.row.col.f32.bf16.bf16.f32 "
        "{%0,%1,%2,%3}, {%4,%5,%6,%7}, {%8,%9}, {%0,%1,%2,%3};"
        : "+f"(d[0]), "+f"(d[1]), "+f"(d[2]), "+f"(d[3])
        : "r"(a[0]), "r"(a[1]), "r"(a[2]), "r"(a[3]), "r"(b[0]), "r"(b[1]));
}
__device__ __forceinline__ void ldsm4(uint32_t* r, uint32_t addr) {
    asm volatile("ldmatrix.sync.aligned.m8n8.x4.shared.b16 {%0,%1,%2,%3}, [%4];"
                 : "=r"(r[0]), "=r"(r[1]), "=r"(r[2]), "=r"(r[3]) : "r"(addr));
}
__device__ __forceinline__ uint32_t smem_u32(const void* p) {
    uint32_t a;
    asm("{ .reg .u64 t; cvta.to.shared.u64 t, %1; cvt.u32.u64 %0, t; }"
        : "=r"(a) : "l"(p));
    return a;
}
__device__ __forceinline__ void cpa16(uint32_t dst, const void* src, int srcsize) {
    asm volatile("cp.async.cg.shared.global [%0], [%1], 16, %2;"
                 :: "r"(dst), "l"(src), "r"(srcsize) : "memory");
}
#define CP_COMMIT() asm volatile("cp.async.commit_group;" ::: "memory")
#define CP_WAIT1()  asm volatile("cp.async.wait_group 1;" ::: "memory")
#define CP_WAIT0()  asm volatile("cp.async.wait_group 0;" ::: "memory")

// ---------------------------------------------------------------------------
// Pipelined HMMA matmul: D[128 spatial][128 out-ch] per CTA, K-chunk 32.
// Smem tiles [row][16 u32] stride 20 u32 (80B) -> ldmatrix conflict-free.
// 2-stage cp.async double buffer. Stage: Ah|Al|Bh|Bl x 10240B = 40960B.
// Inner schedule: 3 waves of 16 independent mmas (dep distance 16, B frags
// resident) to keep the tensor pipe fed.
// OUTM: 0 packed hi/lo [n][cpair]; 1 fp32 [n][ldoutF]; 2 fp32 [c][ldoutF]
//       (smem-staged transpose for coalesced stores).
// ---------------------------------------------------------------------------
#define TILE_B 10240
#define STAGE_B 40960

template<bool CONV, int OUTM, bool SILU, bool BIASF>
__global__ void __launch_bounds__(256, 2) mm_hmma(
    const uint32_t* __restrict__ Ahi, const uint32_t* __restrict__ Alo,
    int ldap, int apbase,
    const uint32_t* __restrict__ Bhi, const uint32_t* __restrict__ Blo, int ldbp,
    const float* __restrict__ bias,
    float* __restrict__ outF, int ldoutF, long outFb,
    uint32_t* __restrict__ Ohi, uint32_t* __restrict__ Olo, int ldop, int opbase,
    int Ktot)
{
    extern __shared__ char smem[];
    const uint32_t sbase = smem_u32(smem);

    const int tid  = threadIdx.x;
    const int lane = tid & 31;
    const int wid  = tid >> 5;
    const int g    = lane >> 2;
    const int t4   = lane & 3;
    const int m0w  = (wid & 1) * 64;
    const int n0w  = (wid >> 1) * 32;
    const int n0 = blockIdx.x * 128, c0 = blockIdx.y * 128, b = blockIdx.z;

    Ahi += (size_t)b * 4096 * ldap;
    Alo += (size_t)b * 4096 * ldap;

    const int rit = lane & 7, sel = lane >> 3;
    const uint32_t aFragBase = (uint32_t)((m0w + (sel & 1) * 8 + rit) * 80 + (sel >> 1) * 16);
    const uint32_t bFragBase = (uint32_t)((n0w + (sel >> 1) * 8 + rit) * 80 + (sel & 1) * 16);

    float acc[4][4][4] = {};
    const int NC = Ktot >> 5;

    auto load_chunk = [&](int ch, int st) {
        const uint32_t stAh = sbase + st * STAGE_B;
        const uint32_t stAl = stAh + TILE_B;
        const uint32_t stBh = stAh + 2 * TILE_B;
        const uint32_t stBl = stAh + 3 * TILE_B;
        int cp0;
        int dy = 0, dx = 0;
        if (CONV) { int t9 = ch >> 3; dy = t9 / 3; dx = t9 - dy * 3; cp0 = (ch & 7) * 16; }
        else      { cp0 = ch * 16; }
        #pragma unroll
        for (int r = 0; r < 2; r++) {
            const int idx = tid + 256 * r;
            const int row = idx >> 2, q = idx & 3;
            int srcRow = n0 + row;
            int vsz = 16;
            if (CONV) {
                const int nn = n0 + row;
                const int yy = (nn >> 6) + dy - 1, xx = (nn & 63) + dx - 1;
                if (((unsigned)yy >= 64u) || ((unsigned)xx >= 64u)) vsz = 0;
                srcRow = yy * 64 + xx;
            }
            const size_t aoff = (size_t)srcRow * ldap + apbase + cp0 + q * 4;
            cpa16(stAh + row * 80 + q * 16, Ahi + aoff, vsz);
            cpa16(stAl + row * 80 + q * 16, Alo + aoff, vsz);
            const size_t boff = (size_t)(c0 + row) * ldbp + ch * 16 + q * 4;
            cpa16(stBh + row * 80 + q * 16, Bhi + boff, 16);
            cpa16(stBl + row * 80 + q * 16, Blo + boff, 16);
        }
    };

    load_chunk(0, 0);
    CP_COMMIT();

    for (int ch = 0; ch < NC; ch++) {
        const int st = ch & 1;
        if (ch + 1 < NC) { load_chunk(ch + 1, st ^ 1); CP_COMMIT(); CP_WAIT1(); }
        else             { CP_WAIT0(); }
        __syncthreads();

        const uint32_t stAh = sbase + st * STAGE_B;
        const uint32_t stAl = stAh + TILE_B;
        const uint32_t stBh = stAh + 2 * TILE_B;
        const uint32_t stBl = stAh + 3 * TILE_B;

        #pragma unroll
        for (int ks = 0; ks < 2; ks++) {
            const uint32_t ko = ks * 32;
            uint32_t a[4][4], bh[2][4], bl[2][4];
            #pragma unroll
            for (int mf = 0; mf < 4; mf++)
                ldsm4(a[mf], stAh + aFragBase + mf * 1280 + ko);
            #pragma unroll
            for (int nfp = 0; nfp < 2; nfp++) {
                ldsm4(bh[nfp], stBh + bFragBase + nfp * 1280 + ko);
                ldsm4(bl[nfp], stBl + bFragBase + nfp * 1280 + ko);
            }
            // wave 1: hiA * hiB — 16 independent accumulators
            #pragma unroll
            for (int mf = 0; mf < 4; mf++)
                #pragma unroll
                for (int nfp = 0; nfp < 2; nfp++) {
                    mma16816(acc[mf][2 * nfp],     a[mf], bh[nfp]);
                    mma16816(acc[mf][2 * nfp + 1], a[mf], bh[nfp] + 2);
                }
            // wave 2: hiA * loB
            #pragma unroll
            for (int mf = 0; mf < 4; mf++)
                #pragma unroll
                for (int nfp = 0; nfp < 2; nfp++) {
                    mma16816(acc[mf][2 * nfp],     a[mf], bl[nfp]);
                    mma16816(acc[mf][2 * nfp + 1], a[mf], bl[nfp] + 2);
                }
            // wave 3: loA * hiB (B frags stay resident)
            #pragma unroll
            for (int mf = 0; mf < 4; mf++)
                ldsm4(a[mf], stAl + aFragBase + mf * 1280 + ko);
            #pragma unroll
            for (int mf = 0; mf < 4; mf++)
                #pragma unroll
                for (int nfp = 0; nfp < 2; nfp++) {
                    mma16816(acc[mf][2 * nfp],     a[mf], bh[nfp]);
                    mma16816(acc[mf][2 * nfp + 1], a[mf], bh[nfp] + 2);
                }
        }
        __syncthreads();
    }

    // ---- epilogue (batch pointer adjust deferred here to save regs) ----
    if (OUTM == 0) { Ohi += (size_t)b * 4096 * ldop; Olo += (size_t)b * 4096 * ldop; }
    float* oF = outF + (size_t)b * outFb;
    float* sst = (float*)smem;   // OUTM==2 staging (stages are dead now)

    #pragma unroll
    for (int mf = 0; mf < 4; mf++) {
        const int rl = m0w + mf * 16 + g;        // local row 0..127
        const int r0 = n0 + rl;
        #pragma unroll
        for (int nf = 0; nf < 4; nf++) {
            const int ncl = n0w + nf * 8 + t4 * 2;   // local col (even)
            const int ncol = c0 + ncl;
            float v00 = acc[mf][nf][0], v01 = acc[mf][nf][1];
            float v10 = acc[mf][nf][2], v11 = acc[mf][nf][3];
            if (BIASF) {
                const float b0f = bias[ncol], b1f = bias[ncol + 1];
                v00 += b0f; v01 += b1f; v10 += b0f; v11 += b1f;
            }
            if (SILU) {
                v00 = silu_f(v00); v01 = silu_f(v01);
                v10 = silu_f(v10); v11 = silu_f(v11);
            }
            if (OUTM == 0) {
                uint32_t hp, lp;
                pack2(v00, v01, hp, lp);
                const size_t i0 = (size_t)r0 * ldop + opbase + (ncol >> 1);
                Ohi[i0] = hp; Olo[i0] = lp;
                pack2(v10, v11, hp, lp);
                const size_t i1 = (size_t)(r0 + 8) * ldop + opbase + (ncol >> 1);
                Ohi[i1] = hp; Olo[i1] = lp;
            } else if (OUTM == 1) {
                *(float2*)(oF + (size_t)r0 * ldoutF + ncol)       = make_float2(v00, v01);
                *(float2*)(oF + (size_t)(r0 + 8) * ldoutF + ncol) = make_float2(v10, v11);
            } else {
                sst[ncl * 132 + rl]           = v00;
                sst[(ncl + 1) * 132 + rl]     = v01;
                sst[ncl * 132 + rl + 8]       = v10;
                sst[(ncl + 1) * 132 + rl + 8] = v11;
            }
        }
    }
    if (OUTM == 2) {
        __syncthreads();
        #pragma unroll
        for (int rnd = 0; rnd < 16; rnd++) {
            const int c = wid * 16 + rnd;
            float4 v = *(float4*)&sst[c * 132 + lane * 4];
            *(float4*)(oF + (size_t)(c0 + c) * ldoutF + n0 + lane * 4) = v;
        }
    }
}

// ---------------------------------------------------------------------------
// One merged prepack kernel: all weights + fused projection weights + bias.
// ---------------------------------------------------------------------------
__global__ void prepack_all_k(
    const float* __restrict__ cv1_w, const float* __restrict__ cv2_w,
    const float* __restrict__ vproj_w, const float* __restrict__ off_w,
    const float* __restrict__ aw_w, const float* __restrict__ vproj_b,
    const float* __restrict__ off_b, const float* __restrict__ aw_b,
    const float* __restrict__ out_w,
    const float* __restrict__ mc0, const float* __restrict__ mc1,
    const float* __restrict__ mc2, const float* __restrict__ mc3,
    uint32_t* __restrict__ wcv1_h, uint32_t* __restrict__ wcv1_l,
    uint32_t* __restrict__ wcv2_h, uint32_t* __restrict__ wcv2_l,
    uint32_t* __restrict__ wpj_h,  uint32_t* __restrict__ wpj_l,
    uint32_t* __restrict__ wop_h,  uint32_t* __restrict__ wop_l,
    uint32_t* __restrict__ wc_h,   uint32_t* __restrict__ wc_l,
    float* __restrict__ biasc)
{
    const int idx = blockIdx.x * 256 + threadIdx.x;
    const int R0 = 512 * 256;
    const int R1 = R0 + 512 * 640;
    const int R2 = R1 + 384 * 128;
    const int R3 = R2 + 256 * 128;
    const int R4 = R3 + 4 * 256 * 1152;
    const int R5 = R4 + 384;
    if (idx < R0) {
        const int co = idx >> 8, kp = idx & 255;
        uint32_t hp, lp;
        pack2(cv1_w[(size_t)co * 512 + 2 * kp], cv1_w[(size_t)co * 512 + 2 * kp + 1], hp, lp);
        wcv1_h[idx] = hp; wcv1_l[idx] = lp;
    } else if (idx < R1) {
        const int j = idx - R0, co = j / 640, kp = j - co * 640;
        uint32_t hp, lp;
        pack2(cv2_w[(size_t)co * 1280 + 2 * kp], cv2_w[(size_t)co * 1280 + 2 * kp + 1], hp, lp);
        wcv2_h[j] = hp; wcv2_l[j] = lp;
    } else if (idx < R2) {
        const int j = idx - R1, co = j >> 7, kp = j & 127;
        float v0 = 0.f, v1 = 0.f;
        if (co < 256)      { v0 = vproj_w[(size_t)(2*kp)*256 + co];     v1 = vproj_w[(size_t)(2*kp+1)*256 + co]; }
        else if (co < 320) { const int c = co - 256;
                             v0 = off_w[(size_t)(2*kp)*64 + c];         v1 = off_w[(size_t)(2*kp+1)*64 + c]; }
        else if (co < 352) { const int c = co - 320;
                             v0 = aw_w[(size_t)(2*kp)*32 + c];          v1 = aw_w[(size_t)(2*kp+1)*32 + c]; }
        uint32_t hp, lp; pack2(v0, v1, hp, lp);
        wpj_h[j] = hp; wpj_l[j] = lp;
    } else if (idx < R3) {
        const int j = idx - R2, co = j >> 7, kp = j & 127;
        uint32_t hp, lp;
        pack2(out_w[(size_t)(2*kp)*256 + co], out_w[(size_t)(2*kp+1)*256 + co], hp, lp);
        wop_h[j] = hp; wop_l[j] = lp;
    } else if (idx < R4) {
        const int j = idx - R3;
        const int which = j / (256 * 1152), r = j - which * (256 * 1152);
        const int co = r / 1152, kp = r - co * 1152;
        const int t = kp >> 7, cp = kp & 127;
        const float* W = which == 0 ? mc0 : which == 1 ? mc1 : which == 2 ? mc2 : mc3;
        uint32_t hp, lp;
        pack2(W[(size_t)co * 2304 + (2*cp)*9 + t], W[(size_t)co * 2304 + (2*cp+1)*9 + t], hp, lp);
        wc_h[j] = hp; wc_l[j] = lp;
    } else if (idx < R5) {
        const int j = idx - R4;
        biasc[j] = j < 256 ? vproj_b[j] : j < 320 ? off_b[j - 256]
                 : j < 352 ? aw_b[j - 320] : 0.f;
    }
}

// x (B,512,4096) -> packed [b*4096+n][256] via smem transpose
__global__ void prepack_x_k(const float* __restrict__ x,
                            uint32_t* __restrict__ xh, uint32_t* __restrict__ xl)
{
    __shared__ uint32_t th[32][33], tl[32][33];
    const int tx = threadIdx.x, ty = threadIdx.y;
    const int n0 = blockIdx.x * 32, cp0 = blockIdx.y * 32, b = blockIdx.z;
    const float* xb = x + (size_t)b * 512 * 4096;
    #pragma unroll
    for (int k = 0; k < 4; k++) {
        const int cp = cp0 + ty + k * 8;
        const float v0 = xb[(size_t)(2 * cp) * 4096 + n0 + tx];
        const float v1 = xb[(size_t)(2 * cp + 1) * 4096 + n0 + tx];
        uint32_t hp, lp; pack2(v0, v1, hp, lp);
        th[ty + k * 8][tx] = hp; tl[ty + k * 8][tx] = lp;
    }
    __syncthreads();
    #pragma unroll
    for (int k = 0; k < 4; k++) {
        const int n = n0 + ty + k * 8;
        const size_t o = ((size_t)b * 4096 + n) * 256 + cp0 + tx;
        xh[o] = th[tx][ty + k * 8];
        xl[o] = tl[tx][ty + k * 8];
    }
}

// ---------------------------------------------------------------------------
// Deformable sampling from fused projection buffer -> packed hi/lo output
// pj row layout: [val 0..255 | off 256..319 | aw 320..351 | pad], stride 384
// ---------------------------------------------------------------------------
__global__ void __launch_bounds__(256) msda_sample_k(
    const float* __restrict__ pj, const float* __restrict__ bbox,
    uint32_t* __restrict__ smpH, uint32_t* __restrict__ smpL)
{
    const int bl   = blockIdx.x;
    const int h    = threadIdx.x >> 5;
    const int lane = threadIdx.x & 31;
    const float* offp = pj + (size_t)bl * 384 + 256 + h * 8;
    const float* awp  = pj + (size_t)bl * 384 + 320 + h * 4;
    const float bx = bbox[(size_t)bl * 2 + 0];
    const float by = bbox[(size_t)bl * 2 + 1];

    float a0 = awp[0], a1 = awp[1], a2 = awp[2], a3 = awp[3];
    float mx = fmaxf(fmaxf(a0, a1), fmaxf(a2, a3));
    float e0 = __expf(a0 - mx), e1 = __expf(a1 - mx);
    float e2 = __expf(a2 - mx), e3 = __expf(a3 - mx);
    float inv = 1.f / (e0 + e1 + e2 + e3);
    float awv[4] = {e0 * inv, e1 * inv, e2 * inv, e3 * inv};

    const int b = bl >> 12;
    const float* vb = pj + (size_t)b * 4096 * 384 + h * 32 + lane;
    float acc = 0.f;
    #pragma unroll
    for (int p = 0; p < 4; p++) {
        float gx = (bx + offp[p * 2 + 0] * (1.f / 64.f)) * 64.f - 0.5f;
        float gy = (by + offp[p * 2 + 1] * (1.f / 64.f)) * 64.f - 0.5f;
        float x0f = floorf(gx), y0f = floorf(gy);
        float wx1 = gx - x0f, wy1 = gy - y0f;
        float wx0 = 1.f - wx1, wy0 = 1.f - wy1;
        int x0 = (int)x0f, y0 = (int)y0f;
        float s = 0.f;
        if ((unsigned)x0 < 64u && (unsigned)y0 < 64u)
            s += wx0 * wy0 * vb[(size_t)(y0 * 64 + x0) * 384];
        if ((unsigned)(x0 + 1) < 64u && (unsigned)y0 < 64u)
            s += wx1 * wy0 * vb[(size_t)(y0 * 64 + x0 + 1) * 384];
        if ((unsigned)x0 < 64u && (unsigned)(y0 + 1) < 64u)
            s += wx0 * wy1 * vb[(size_t)((y0 + 1) * 64 + x0) * 384];
        if ((unsigned)(x0 + 1) < 64u && (unsigned)(y0 + 1) < 64u)
            s += wx1 * wy1 * vb[(size_t)((y0 + 1) * 64 + x0 + 1) * 384];
        acc += awv[p] * s;
    }
    const float vOdd = __shfl_down_sync(0xffffffffu, acc, 1);
    if ((lane & 1) == 0) {
        uint32_t hp, lp; pack2(acc, vOdd, hp, lp);
        const size_t o = (size_t)bl * 128 + h * 16 + (lane >> 1);
        smpH[o] = hp; smpL[o] = lp;
    }
}

// ---------------------------------------------------------------------------
extern "C" void kernel_launch(void* const* d_in, const int* in_sizes, int n_in,
                              void* d_out, int out_size)
{
    const float* x       = (const float*)d_in[0];
    const float* bbox    = (const float*)d_in[1];
    const float* cv1_w   = (const float*)d_in[3];
    const float* mc0     = (const float*)d_in[4];
    const float* mc1     = (const float*)d_in[5];
    const float* mc2     = (const float*)d_in[6];
    const float* mc3     = (const float*)d_in[7];
    const float* vproj_w = (const float*)d_in[8];
    const float* vproj_b = (const float*)d_in[9];
    const float* off_w   = (const float*)d_in[10];
    const float* off_b   = (const float*)d_in[11];
    const float* aw_w    = (const float*)d_in[12];
    const float* aw_b    = (const float*)d_in[13];
    const float* out_w   = (const float*)d_in[14];
    const float* out_b   = (const float*)d_in[15];
    const float* cv2_w   = (const float*)d_in[16];
    float* out = (float*)d_out;

    uint32_t *xp_h, *xp_l, *catp_h, *catp_l, *s0p_h, *s0p_l, *smpp_h, *smpp_l;
    uint32_t *wcv1_h, *wcv1_l, *wcv2_h, *wcv2_l, *wpj_h, *wpj_l, *wop_h, *wop_l;
    uint32_t *wc_h, *wc_l;
    float *pj, *biasc;
    cudaGetSymbolAddress((void**)&xp_h, g_xp_h);   cudaGetSymbolAddress((void**)&xp_l, g_xp_l);
    cudaGetSymbolAddress((void**)&catp_h, g_catp_h); cudaGetSymbolAddress((void**)&catp_l, g_catp_l);
    cudaGetSymbolAddress((void**)&s0p_h, g_s0p_h); cudaGetSymbolAddress((void**)&s0p_l, g_s0p_l);
    cudaGetSymbolAddress((void**)&smpp_h, g_smpp_h); cudaGetSymbolAddress((void**)&smpp_l, g_smpp_l);
    cudaGetSymbolAddress((void**)&wcv1_h, g_wcv1_h); cudaGetSymbolAddress((void**)&wcv1_l, g_wcv1_l);
    cudaGetSymbolAddress((void**)&wcv2_h, g_wcv2_h); cudaGetSymbolAddress((void**)&wcv2_l, g_wcv2_l);
    cudaGetSymbolAddress((void**)&wpj_h, g_wpj_h); cudaGetSymbolAddress((void**)&wpj_l, g_wpj_l);
    cudaGetSymbolAddress((void**)&wop_h, g_wop_h); cudaGetSymbolAddress((void**)&wop_l, g_wop_l);
    cudaGetSymbolAddress((void**)&wc_h, g_wc_h);   cudaGetSymbolAddress((void**)&wc_l, g_wc_l);
    cudaGetSymbolAddress((void**)&pj, g_pj);
    cudaGetSymbolAddress((void**)&biasc, g_biasc);

    const int DYN = 2 * STAGE_B;   // 81920
    cudaFuncSetAttribute(mm_hmma<false,0,true ,false>, cudaFuncAttributeMaxDynamicSharedMemorySize, DYN);
    cudaFuncSetAttribute(mm_hmma<true ,0,true ,false>, cudaFuncAttributeMaxDynamicSharedMemorySize, DYN);
    cudaFuncSetAttribute(mm_hmma<false,1,false,true >, cudaFuncAttributeMaxDynamicSharedMemorySize, DYN);
    cudaFuncSetAttribute(mm_hmma<false,0,false,true >, cudaFuncAttributeMaxDynamicSharedMemorySize, DYN);
    cudaFuncSetAttribute(mm_hmma<false,2,true ,false>, cudaFuncAttributeMaxDynamicSharedMemorySize, DYN);

    // launch 0: all weight prepack + fused bias
    {
        const int total = 512*256 + 512*640 + 384*128 + 256*128 + 4*256*1152 + 384;
        prepack_all_k<<<(total + 255) / 256, 256>>>(
            cv1_w, cv2_w, vproj_w, off_w, aw_w, vproj_b, off_b, aw_b, out_w,
            mc0, mc1, mc2, mc3,
            wcv1_h, wcv1_l, wcv2_h, wcv2_l, wpj_h, wpj_l, wop_h, wop_l,
            wc_h, wc_l, biasc);
    }
    // launch 1: input prepack
    prepack_x_k<<<dim3(128, 8, NB), dim3(32, 8)>>>(x, xp_h, xp_l);

    // launch 2: cv1 -> cat [a|b] (pairs 0..255), SiLU
    mm_hmma<false,0,true,false><<<dim3(32, 4, NB), 256, DYN>>>(
        xp_h, xp_l, 256, 0, wcv1_h, wcv1_l, 256, nullptr,
        nullptr, 0, 0, catp_h, catp_l, 640, 0, 512);

    // launches 3-6: bottleneck convs b -> b1 -> b2
    mm_hmma<true,0,true,false><<<dim3(32, 2, NB), 256, DYN>>>(
        catp_h, catp_l, 640, 128, wc_h + 0*256*1152, wc_l + 0*256*1152, 1152, nullptr,
        nullptr, 0, 0, s0p_h, s0p_l, 128, 0, 2304);
    mm_hmma<true,0,true,false><<<dim3(32, 2, NB), 256, DYN>>>(
        s0p_h, s0p_l, 128, 0, wc_h + 1*256*1152, wc_l + 1*256*1152, 1152, nullptr,
        nullptr, 0, 0, catp_h, catp_l, 640, 256, 2304);
    mm_hmma<true,0,true,false><<<dim3(32, 2, NB), 256, DYN>>>(
        catp_h, catp_l, 640, 256, wc_h + 2*256*1152, wc_l + 2*256*1152, 1152, nullptr,
        nullptr, 0, 0, s0p_h, s0p_l, 128, 0, 2304);
    mm_hmma<true,0,true,false><<<dim3(32, 2, NB), 256, DYN>>>(
        s0p_h, s0p_l, 128, 0, wc_h + 3*256*1152, wc_l + 3*256*1152, 1152, nullptr,
        nullptr, 0, 0, catp_h, catp_l, 640, 384, 2304);

    // launch 7: fused projections (val|off|aw), fp32 out [row][384] + bias
    mm_hmma<false,1,false,true><<<dim3(32, 3, NB), 256, DYN>>>(
        catp_h, catp_l, 640, 384, wpj_h, wpj_l, 128, biasc,
        pj, 384, 4096L*384, nullptr, nullptr, 0, 0, 256);

    // launch 8: deformable sampling -> packed smp
    msda_sample_k<<<NB * HWN, 256>>>(pj, bbox, smpp_h, smpp_l);

    // launch 9: output projection -> cat attn section (pairs 512..639)
    mm_hmma<false,0,false,true><<<dim3(32, 2, NB), 256, DYN>>>(
        smpp_h, smpp_l, 128, 0, wop_h, wop_l, 128, out_b,
        nullptr, 0, 0, catp_h, catp_l, 640, 512, 256);

    // launch 10: cv2 K=1280, SiLU, channel-major fp32 out (coalesced via smem)
    mm_hmma<false,2,true,false><<<dim3(32, 4, NB), 256, DYN>>>(
        catp_h, catp_l, 640, 0, wcv2_h, wcv2_l, 640, nullptr,
        out, 4096, 512L*4096, nullptr, nullptr, 0, 0, 1280);
}

// round 12
// speedup vs baseline: 1.0052x; 1.0052x over previous
#include <cuda_runtime.h>
#include <cuda_bf16.h>
#include <cstdint>

// ---------------------------------------------------------------------------
// C2fDA via legacy HMMA (mma.sync m16n8k16 bf16), cp.async pipelined +
// ldmatrix fragments. Split-3 hi/lo bf16, fp32 accum (err ~1e-5).
// Round 12: register-tight loader (u32 incremental offsets, no lambda).
// B=8, C1=512, C=256, D=256, NH=8, NP=4, NL=1, H=W=64, L=4096
// ---------------------------------------------------------------------------

#define NB 8
#define HWN 4096

// ---------------- scratch (allocation-guard-safe) --------------------------
__device__ uint32_t g_xp_h [(size_t)NB*4096*256];
__device__ uint32_t g_xp_l [(size_t)NB*4096*256];
__device__ uint32_t g_catp_h[(size_t)NB*4096*640];   // [a|b|b1|b2|attn] pairs
__device__ uint32_t g_catp_l[(size_t)NB*4096*640];
__device__ uint32_t g_s0p_h[(size_t)NB*4096*128];
__device__ uint32_t g_s0p_l[(size_t)NB*4096*128];
__device__ uint32_t g_smpp_h[(size_t)NB*4096*128];
__device__ uint32_t g_smpp_l[(size_t)NB*4096*128];
__device__ float    g_pj   [(size_t)NB*4096*384];    // [val 256 | off 64 | aw 32 | pad 32]
__device__ uint32_t g_wcv1_h[512*256],  g_wcv1_l[512*256];
__device__ uint32_t g_wcv2_h[512*640],  g_wcv2_l[512*640];
__device__ uint32_t g_wpj_h [384*128],  g_wpj_l [384*128];
__device__ uint32_t g_wop_h [256*128],  g_wop_l [256*128];
__device__ uint32_t g_wc_h  [4*256*1152], g_wc_l[4*256*1152];
__device__ float    g_biasc [384];

__device__ __forceinline__ float silu_f(float x) { return x / (1.f + __expf(-x)); }

__device__ __forceinline__ void hilo16(float v, unsigned short& h, unsigned short& l) {
    __nv_bfloat16 hb = __float2bfloat16(v);
    float res = v - __bfloat162float(hb);
    __nv_bfloat16 lb = __float2bfloat16(res);
    h = __bfloat16_as_ushort(hb); l = __bfloat16_as_ushort(lb);
}
__device__ __forceinline__ void pack2(float v0, float v1, uint32_t& hp, uint32_t& lp) {
    unsigned short h0, l0, h1, l1;
    hilo16(v0, h0, l0); hilo16(v1, h1, l1);
    hp = ((uint32_t)h1 << 16) | h0;
    lp = ((uint32_t)l1 << 16) | l0;
}

__device__ __forceinline__ void mma16816(float* d, const uint32_t* a, const uint32_t* b) {
    asm volatile(
        "mma.sync.aligned.m16n8k16.row.col.f32.bf16.bf16.f32 "
        "{%0,%1,%2,%3}, {%4,%5,%6,%7}, {%8,%9}, {%0,%1,%2,%3};"
        : "+f"(d[0]), "+f"(d[1]), "+f"(d[2]), "+f"(d[3])
        : "r"(a[0]), "r"(a[1]), "r"(a[2]), "r"(a[3]), "r"(b[0]), "r"(b[1]));
}
__device__ __forceinline__ void ldsm4(uint32_t* r, uint32_t addr) {
    asm volatile("ldmatrix.sync.aligned.m8n8.x4.shared.b16 {%0,%1,%2,%3}, [%4];"
                 : "=r"(r[0]), "=r"(r[1]), "=r"(r[2]), "=r"(r[3]) : "r"(addr));
}
__device__ __forceinline__ uint32_t smem_u32(const void* p) {
    uint32_t a;
    asm("{ .reg .u64 t; cvta.to.shared.u64 t, %1; cvt.u32.u64 %0, t; }"
        : "=r"(a) : "l"(p));
    return a;
}
__device__ __forceinline__ void cpa16(uint32_t dst, const void* src, int srcsize) {
    asm volatile("cp.async.cg.shared.global [%0], [%1], 16, %2;"
                 :: "r"(dst), "l"(src), "r"(srcsize) : "memory");
}
#define CP_COMMIT() asm volatile("cp.async.commit_group;" ::: "memory")
#define CP_WAIT1()  asm volatile("cp.async.wait_group 1;" ::: "memory")
#define CP_WAIT0()  asm volatile("cp.async.wait_group 0;" ::: "memory")

// ---------------------------------------------------------------------------
// Pipelined HMMA matmul: D[128 spatial][128 out-ch] per CTA, K-chunk 32.
// Smem tiles [row][16 u32] stride 20 u32 (80B) -> ldmatrix conflict-free.
// 2-stage cp.async double buffer. Stage: Ah|Al|Bh|Bl x 10240B = 40960B.
// Loader keeps 4 incremental u32 offsets per thread (no 64-bit recompute)
// so the in-loop live set stays below the 128-reg cap (no spills).
// OUTM: 0 packed hi/lo [n][cpair]; 1 fp32 [n][ldoutF]; 2 fp32 [c][ldoutF].
// ---------------------------------------------------------------------------
#define TILE_B 10240
#define STAGE_B 40960

template<bool CONV, int OUTM, bool SILU, bool BIASF>
__global__ void __launch_bounds__(256, 2) mm_hmma(
    const uint32_t* __restrict__ Ahi, const uint32_t* __restrict__ Alo,
    int ldap, int apbase,
    const uint32_t* __restrict__ Bhi, const uint32_t* __restrict__ Blo, int ldbp,
    const float* __restrict__ bias,
    float* __restrict__ outF, int ldoutF, long outFb,
    uint32_t* __restrict__ Ohi, uint32_t* __restrict__ Olo, int ldop, int opbase,
    int Ktot)
{
    extern __shared__ char smem[];
    const uint32_t sbase = smem_u32(smem);

    const int tid  = threadIdx.x;
    const int lane = tid & 31;
    const int wid  = tid >> 5;
    const int n0 = blockIdx.x * 128, c0 = blockIdx.y * 128, b = blockIdx.z;

    Ahi += (size_t)b * 4096 * ldap;
    Alo += (size_t)b * 4096 * ldap;

    const int rit = lane & 7, sel = lane >> 3;
    const int m0w  = (wid & 1) * 64;
    const int n0w  = (wid >> 1) * 32;
    const uint32_t aFragBase = sbase + (uint32_t)((m0w + (sel & 1) * 8 + rit) * 80 + (sel >> 1) * 16);
    const uint32_t bFragBase = sbase + 2u * TILE_B +
                               (uint32_t)((n0w + (sel >> 1) * 8 + rit) * 80 + (sel & 1) * 16);

    // ---- loader per-thread state (u32, incremental) ----
    const int lrow = tid >> 2;             // 0..63 (second row = lrow+64)
    const uint32_t dRel = (uint32_t)(lrow * 80 + (tid & 3) * 16);
    uint32_t offA0, offA1, offB0, offB1;
    int vsz0 = 16, vsz1 = 16;

    offB0 = (uint32_t)((c0 + lrow) * ldbp + (tid & 3) * 4);
    offB1 = offB0 + (uint32_t)(64 * ldbp);
    if (CONV) {
        // tap 0: dy=0, dx=0 -> shift (-1,-1)
        const int nn0 = n0 + lrow, nn1 = nn0 + 64;
        int yy = (nn0 >> 6) - 1, xx = (nn0 & 63) - 1;
        vsz0 = (((unsigned)yy < 64u) && ((unsigned)xx < 64u)) ? 16 : 0;
        offA0 = (uint32_t)((yy * 64 + xx) * ldap + apbase + (tid & 3) * 4);
        yy = (nn1 >> 6) - 1; xx = (nn1 & 63) - 1;
        vsz1 = (((unsigned)yy < 64u) && ((unsigned)xx < 64u)) ? 16 : 0;
        offA1 = (uint32_t)((yy * 64 + xx) * ldap + apbase + (tid & 3) * 4);
    } else {
        offA0 = (uint32_t)((n0 + lrow) * ldap + apbase + (tid & 3) * 4);
        offA1 = offA0 + (uint32_t)(64 * ldap);
    }

    float acc[4][4][4] = {};
    const int NC = Ktot >> 5;

    // ---- prologue: load chunk 0 into stage 0 ----
    {
        const uint32_t d0 = sbase + dRel;
        cpa16(d0,                    Ahi + offA0, vsz0);
        cpa16(d0 + 5120,             Ahi + offA1, vsz1);
        cpa16(d0 + TILE_B,           Alo + offA0, vsz0);
        cpa16(d0 + TILE_B + 5120,    Alo + offA1, vsz1);
        cpa16(d0 + 2*TILE_B,         Bhi + offB0, 16);
        cpa16(d0 + 2*TILE_B + 5120,  Bhi + offB1, 16);
        cpa16(d0 + 3*TILE_B,         Blo + offB0, 16);
        cpa16(d0 + 3*TILE_B + 5120,  Blo + offB1, 16);
    }
    CP_COMMIT();
    // advance offsets -> chunk 1
    if (CONV) {
        // chunk 1 is still tap 0 (8 chunks per tap)
        offA0 += 16; offA1 += 16;
    } else { offA0 += 16; offA1 += 16; }
    offB0 += 16; offB1 += 16;

    for (int ch = 0; ch < NC; ch++) {
        const int st = ch & 1;
        if (ch + 1 < NC) {
            const uint32_t d0 = sbase + (st ^ 1) * STAGE_B + dRel;
            cpa16(d0,                    Ahi + offA0, vsz0);
            cpa16(d0 + 5120,             Ahi + offA1, vsz1);
            cpa16(d0 + TILE_B,           Alo + offA0, vsz0);
            cpa16(d0 + TILE_B + 5120,    Alo + offA1, vsz1);
            cpa16(d0 + 2*TILE_B,         Bhi + offB0, 16);
            cpa16(d0 + 2*TILE_B + 5120,  Bhi + offB1, 16);
            cpa16(d0 + 3*TILE_B,         Blo + offB0, 16);
            cpa16(d0 + 3*TILE_B + 5120,  Blo + offB1, 16);
            CP_COMMIT();
            // advance to chunk ch+2
            const int nxt = ch + 2;
            if (CONV && ((nxt & 7) == 0)) {
                const int t9 = nxt >> 3;
                const int dy = t9 / 3, dx = t9 - dy * 3;
                const int nn0 = n0 + lrow, nn1 = nn0 + 64;
                int yy = (nn0 >> 6) + dy - 1, xx = (nn0 & 63) + dx - 1;
                vsz0 = (((unsigned)yy < 64u) && ((unsigned)xx < 64u)) ? 16 : 0;
                offA0 = (uint32_t)((yy * 64 + xx) * ldap + apbase + (tid & 3) * 4);
                yy = (nn1 >> 6) + dy - 1; xx = (nn1 & 63) + dx - 1;
                vsz1 = (((unsigned)yy < 64u) && ((unsigned)xx < 64u)) ? 16 : 0;
                offA1 = (uint32_t)((yy * 64 + xx) * ldap + apbase + (tid & 3) * 4);
            } else {
                offA0 += 16; offA1 += 16;
            }
            offB0 += 16; offB1 += 16;
            CP_WAIT1();
        } else {
            CP_WAIT0();
        }
        __syncthreads();

        const uint32_t stOff = (uint32_t)(st * STAGE_B);
        #pragma unroll
        for (int ks = 0; ks < 2; ks++) {
            const uint32_t ko = stOff + ks * 32;
            uint32_t a[4][4], bh[2][4], bl[2][4];
            #pragma unroll
            for (int mf = 0; mf < 4; mf++)
                ldsm4(a[mf], aFragBase + mf * 1280 + ko);
            #pragma unroll
            for (int nfp = 0; nfp < 2; nfp++) {
                ldsm4(bh[nfp], bFragBase + nfp * 1280 + ko);
                ldsm4(bl[nfp], bFragBase + TILE_B + nfp * 1280 + ko);
            }
            #pragma unroll
            for (int mf = 0; mf < 4; mf++)
                #pragma unroll
                for (int nfp = 0; nfp < 2; nfp++) {
                    mma16816(acc[mf][2 * nfp],     a[mf], bh[nfp]);
                    mma16816(acc[mf][2 * nfp + 1], a[mf], bh[nfp] + 2);
                }
            #pragma unroll
            for (int mf = 0; mf < 4; mf++)
                #pragma unroll
                for (int nfp = 0; nfp < 2; nfp++) {
                    mma16816(acc[mf][2 * nfp],     a[mf], bl[nfp]);
                    mma16816(acc[mf][2 * nfp + 1], a[mf], bl[nfp] + 2);
                }
            #pragma unroll
            for (int mf = 0; mf < 4; mf++)
                ldsm4(a[mf], aFragBase + TILE_B + mf * 1280 + ko);
            #pragma unroll
            for (int mf = 0; mf < 4; mf++)
                #pragma unroll
                for (int nfp = 0; nfp < 2; nfp++) {
                    mma16816(acc[mf][2 * nfp],     a[mf], bh[nfp]);
                    mma16816(acc[mf][2 * nfp + 1], a[mf], bh[nfp] + 2);
                }
        }
        __syncthreads();
    }

    // ---- epilogue ----
    const int g  = lane >> 2;
    const int t4 = lane & 3;
    if (OUTM == 0) { Ohi += (size_t)b * 4096 * ldop; Olo += (size_t)b * 4096 * ldop; }
    float* oF = outF + (size_t)b * outFb;
    float* sst = (float*)smem;   // OUTM==2 staging (stages are dead now)

    #pragma unroll
    for (int mf = 0; mf < 4; mf++) {
        const int rl = m0w + mf * 16 + g;
        const int r0 = n0 + rl;
        #pragma unroll
        for (int nf = 0; nf < 4; nf++) {
            const int ncl = n0w + nf * 8 + t4 * 2;
            const int ncol = c0 + ncl;
            float v00 = acc[mf][nf][0], v01 = acc[mf][nf][1];
            float v10 = acc[mf][nf][2], v11 = acc[mf][nf][3];
            if (BIASF) {
                const float b0f = bias[ncol], b1f = bias[ncol + 1];
                v00 += b0f; v01 += b1f; v10 += b0f; v11 += b1f;
            }
            if (SILU) {
                v00 = silu_f(v00); v01 = silu_f(v01);
                v10 = silu_f(v10); v11 = silu_f(v11);
            }
            if (OUTM == 0) {
                uint32_t hp, lp;
                pack2(v00, v01, hp, lp);
                const size_t i0 = (size_t)r0 * ldop + opbase + (ncol >> 1);
                Ohi[i0] = hp; Olo[i0] = lp;
                pack2(v10, v11, hp, lp);
                const size_t i1 = (size_t)(r0 + 8) * ldop + opbase + (ncol >> 1);
                Ohi[i1] = hp; Olo[i1] = lp;
            } else if (OUTM == 1) {
                *(float2*)(oF + (size_t)r0 * ldoutF + ncol)       = make_float2(v00, v01);
                *(float2*)(oF + (size_t)(r0 + 8) * ldoutF + ncol) = make_float2(v10, v11);
            } else {
                sst[ncl * 132 + rl]           = v00;
                sst[(ncl + 1) * 132 + rl]     = v01;
                sst[ncl * 132 + rl + 8]       = v10;
                sst[(ncl + 1) * 132 + rl + 8] = v11;
            }
        }
    }
    if (OUTM == 2) {
        __syncthreads();
        #pragma unroll
        for (int rnd = 0; rnd < 16; rnd++) {
            const int c = wid * 16 + rnd;
            float4 v = *(float4*)&sst[c * 132 + lane * 4];
            *(float4*)(oF + (size_t)(c0 + c) * ldoutF + n0 + lane * 4) = v;
        }
    }
}

// ---------------------------------------------------------------------------
// One merged prepack kernel: all weights + fused projection weights + bias.
// ---------------------------------------------------------------------------
__global__ void prepack_all_k(
    const float* __restrict__ cv1_w, const float* __restrict__ cv2_w,
    const float* __restrict__ vproj_w, const float* __restrict__ off_w,
    const float* __restrict__ aw_w, const float* __restrict__ vproj_b,
    const float* __restrict__ off_b, const float* __restrict__ aw_b,
    const float* __restrict__ out_w,
    const float* __restrict__ mc0, const float* __restrict__ mc1,
    const float* __restrict__ mc2, const float* __restrict__ mc3,
    uint32_t* __restrict__ wcv1_h, uint32_t* __restrict__ wcv1_l,
    uint32_t* __restrict__ wcv2_h, uint32_t* __restrict__ wcv2_l,
    uint32_t* __restrict__ wpj_h,  uint32_t* __restrict__ wpj_l,
    uint32_t* __restrict__ wop_h,  uint32_t* __restrict__ wop_l,
    uint32_t* __restrict__ wc_h,   uint32_t* __restrict__ wc_l,
    float* __restrict__ biasc)
{
    const int idx = blockIdx.x * 256 + threadIdx.x;
    const int R0 = 512 * 256;
    const int R1 = R0 + 512 * 640;
    const int R2 = R1 + 384 * 128;
    const int R3 = R2 + 256 * 128;
    const int R4 = R3 + 4 * 256 * 1152;
    const int R5 = R4 + 384;
    if (idx < R0) {
        const int co = idx >> 8, kp = idx & 255;
        uint32_t hp, lp;
        pack2(cv1_w[(size_t)co * 512 + 2 * kp], cv1_w[(size_t)co * 512 + 2 * kp + 1], hp, lp);
        wcv1_h[idx] = hp; wcv1_l[idx] = lp;
    } else if (idx < R1) {
        const int j = idx - R0, co = j / 640, kp = j - co * 640;
        uint32_t hp, lp;
        pack2(cv2_w[(size_t)co * 1280 + 2 * kp], cv2_w[(size_t)co * 1280 + 2 * kp + 1], hp, lp);
        wcv2_h[j] = hp; wcv2_l[j] = lp;
    } else if (idx < R2) {
        const int j = idx - R1, co = j >> 7, kp = j & 127;
        float v0 = 0.f, v1 = 0.f;
        if (co < 256)      { v0 = vproj_w[(size_t)(2*kp)*256 + co];     v1 = vproj_w[(size_t)(2*kp+1)*256 + co]; }
        else if (co < 320) { const int c = co - 256;
                             v0 = off_w[(size_t)(2*kp)*64 + c];         v1 = off_w[(size_t)(2*kp+1)*64 + c]; }
        else if (co < 352) { const int c = co - 320;
                             v0 = aw_w[(size_t)(2*kp)*32 + c];          v1 = aw_w[(size_t)(2*kp+1)*32 + c]; }
        uint32_t hp, lp; pack2(v0, v1, hp, lp);
        wpj_h[j] = hp; wpj_l[j] = lp;
    } else if (idx < R3) {
        const int j = idx - R2, co = j >> 7, kp = j & 127;
        uint32_t hp, lp;
        pack2(out_w[(size_t)(2*kp)*256 + co], out_w[(size_t)(2*kp+1)*256 + co], hp, lp);
        wop_h[j] = hp; wop_l[j] = lp;
    } else if (idx < R4) {
        const int j = idx - R3;
        const int which = j / (256 * 1152), r = j - which * (256 * 1152);
        const int co = r / 1152, kp = r - co * 1152;
        const int t = kp >> 7, cp = kp & 127;
        const float* W = which == 0 ? mc0 : which == 1 ? mc1 : which == 2 ? mc2 : mc3;
        uint32_t hp, lp;
        pack2(W[(size_t)co * 2304 + (2*cp)*9 + t], W[(size_t)co * 2304 + (2*cp+1)*9 + t], hp, lp);
        wc_h[j] = hp; wc_l[j] = lp;
    } else if (idx < R5) {
        const int j = idx - R4;
        biasc[j] = j < 256 ? vproj_b[j] : j < 320 ? off_b[j - 256]
                 : j < 352 ? aw_b[j - 320] : 0.f;
    }
}

// x (B,512,4096) -> packed [b*4096+n][256] via smem transpose
__global__ void prepack_x_k(const float* __restrict__ x,
                            uint32_t* __restrict__ xh, uint32_t* __restrict__ xl)
{
    __shared__ uint32_t th[32][33], tl[32][33];
    const int tx = threadIdx.x, ty = threadIdx.y;
    const int n0 = blockIdx.x * 32, cp0 = blockIdx.y * 32, b = blockIdx.z;
    const float* xb = x + (size_t)b * 512 * 4096;
    #pragma unroll
    for (int k = 0; k < 4; k++) {
        const int cp = cp0 + ty + k * 8;
        const float v0 = xb[(size_t)(2 * cp) * 4096 + n0 + tx];
        const float v1 = xb[(size_t)(2 * cp + 1) * 4096 + n0 + tx];
        uint32_t hp, lp; pack2(v0, v1, hp, lp);
        th[ty + k * 8][tx] = hp; tl[ty + k * 8][tx] = lp;
    }
    __syncthreads();
    #pragma unroll
    for (int k = 0; k < 4; k++) {
        const int n = n0 + ty + k * 8;
        const size_t o = ((size_t)b * 4096 + n) * 256 + cp0 + tx;
        xh[o] = th[tx][ty + k * 8];
        xl[o] = tl[tx][ty + k * 8];
    }
}

// ---------------------------------------------------------------------------
// Deformable sampling from fused projection buffer -> packed hi/lo output
// pj row layout: [val 0..255 | off 256..319 | aw 320..351 | pad], stride 384
// ---------------------------------------------------------------------------
__global__ void __launch_bounds__(256) msda_sample_k(
    const float* __restrict__ pj, const float* __restrict__ bbox,
    uint32_t* __restrict__ smpH, uint32_t* __restrict__ smpL)
{
    const int bl   = blockIdx.x;
    const int h    = threadIdx.x >> 5;
    const int lane = threadIdx.x & 31;
    const float* offp = pj + (size_t)bl * 384 + 256 + h * 8;
    const float* awp  = pj + (size_t)bl * 384 + 320 + h * 4;
    const float bx = bbox[(size_t)bl * 2 + 0];
    const float by = bbox[(size_t)bl * 2 + 1];

    float a0 = awp[0], a1 = awp[1], a2 = awp[2], a3 = awp[3];
    float mx = fmaxf(fmaxf(a0, a1), fmaxf(a2, a3));
    float e0 = __expf(a0 - mx), e1 = __expf(a1 - mx);
    float e2 = __expf(a2 - mx), e3 = __expf(a3 - mx);
    float inv = 1.f / (e0 + e1 + e2 + e3);
    float awv[4] = {e0 * inv, e1 * inv, e2 * inv, e3 * inv};

    const int b = bl >> 12;
    const float* vb = pj + (size_t)b * 4096 * 384 + h * 32 + lane;
    float acc = 0.f;
    #pragma unroll
    for (int p = 0; p < 4; p++) {
        float gx = (bx + offp[p * 2 + 0] * (1.f / 64.f)) * 64.f - 0.5f;
        float gy = (by + offp[p * 2 + 1] * (1.f / 64.f)) * 64.f - 0.5f;
        float x0f = floorf(gx), y0f = floorf(gy);
        float wx1 = gx - x0f, wy1 = gy - y0f;
        float wx0 = 1.f - wx1, wy0 = 1.f - wy1;
        int x0 = (int)x0f, y0 = (int)y0f;
        float s = 0.f;
        if ((unsigned)x0 < 64u && (unsigned)y0 < 64u)
            s += wx0 * wy0 * vb[(size_t)(y0 * 64 + x0) * 384];
        if ((unsigned)(x0 + 1) < 64u && (unsigned)y0 < 64u)
            s += wx1 * wy0 * vb[(size_t)(y0 * 64 + x0 + 1) * 384];
        if ((unsigned)x0 < 64u && (unsigned)(y0 + 1) < 64u)
            s += wx0 * wy1 * vb[(size_t)((y0 + 1) * 64 + x0) * 384];
        if ((unsigned)(x0 + 1) < 64u && (unsigned)(y0 + 1) < 64u)
            s += wx1 * wy1 * vb[(size_t)((y0 + 1) * 64 + x0 + 1) * 384];
        acc += awv[p] * s;
    }
    const float vOdd = __shfl_down_sync(0xffffffffu, acc, 1);
    if ((lane & 1) == 0) {
        uint32_t hp, lp; pack2(acc, vOdd, hp, lp);
        const size_t o = (size_t)bl * 128 + h * 16 + (lane >> 1);
        smpH[o] = hp; smpL[o] = lp;
    }
}

// ---------------------------------------------------------------------------
extern "C" void kernel_launch(void* const* d_in, const int* in_sizes, int n_in,
                              void* d_out, int out_size)
{
    const float* x       = (const float*)d_in[0];
    const float* bbox    = (const float*)d_in[1];
    const float* cv1_w   = (const float*)d_in[3];
    const float* mc0     = (const float*)d_in[4];
    const float* mc1     = (const float*)d_in[5];
    const float* mc2     = (const float*)d_in[6];
    const float* mc3     = (const float*)d_in[7];
    const float* vproj_w = (const float*)d_in[8];
    const float* vproj_b = (const float*)d_in[9];
    const float* off_w   = (const float*)d_in[10];
    const float* off_b   = (const float*)d_in[11];
    const float* aw_w    = (const float*)d_in[12];
    const float* aw_b    = (const float*)d_in[13];
    const float* out_w   = (const float*)d_in[14];
    const float* out_b   = (const float*)d_in[15];
    const float* cv2_w   = (const float*)d_in[16];
    float* out = (float*)d_out;

    uint32_t *xp_h, *xp_l, *catp_h, *catp_l, *s0p_h, *s0p_l, *smpp_h, *smpp_l;
    uint32_t *wcv1_h, *wcv1_l, *wcv2_h, *wcv2_l, *wpj_h, *wpj_l, *wop_h, *wop_l;
    uint32_t *wc_h, *wc_l;
    float *pj, *biasc;
    cudaGetSymbolAddress((void**)&xp_h, g_xp_h);   cudaGetSymbolAddress((void**)&xp_l, g_xp_l);
    cudaGetSymbolAddress((void**)&catp_h, g_catp_h); cudaGetSymbolAddress((void**)&catp_l, g_catp_l);
    cudaGetSymbolAddress((void**)&s0p_h, g_s0p_h); cudaGetSymbolAddress((void**)&s0p_l, g_s0p_l);
    cudaGetSymbolAddress((void**)&smpp_h, g_smpp_h); cudaGetSymbolAddress((void**)&smpp_l, g_smpp_l);
    cudaGetSymbolAddress((void**)&wcv1_h, g_wcv1_h); cudaGetSymbolAddress((void**)&wcv1_l, g_wcv1_l);
    cudaGetSymbolAddress((void**)&wcv2_h, g_wcv2_h); cudaGetSymbolAddress((void**)&wcv2_l, g_wcv2_l);
    cudaGetSymbolAddress((void**)&wpj_h, g_wpj_h); cudaGetSymbolAddress((void**)&wpj_l, g_wpj_l);
    cudaGetSymbolAddress((void**)&wop_h, g_wop_h); cudaGetSymbolAddress((void**)&wop_l, g_wop_l);
    cudaGetSymbolAddress((void**)&wc_h, g_wc_h);   cudaGetSymbolAddress((void**)&wc_l, g_wc_l);
    cudaGetSymbolAddress((void**)&pj, g_pj);
    cudaGetSymbolAddress((void**)&biasc, g_biasc);

    const int DYN = 2 * STAGE_B;   // 81920
    cudaFuncSetAttribute(mm_hmma<false,0,true ,false>, cudaFuncAttributeMaxDynamicSharedMemorySize, DYN);
    cudaFuncSetAttribute(mm_hmma<true ,0,true ,false>, cudaFuncAttributeMaxDynamicSharedMemorySize, DYN);
    cudaFuncSetAttribute(mm_hmma<false,1,false,true >, cudaFuncAttributeMaxDynamicSharedMemorySize, DYN);
    cudaFuncSetAttribute(mm_hmma<false,0,false,true >, cudaFuncAttributeMaxDynamicSharedMemorySize, DYN);
    cudaFuncSetAttribute(mm_hmma<false,2,true ,false>, cudaFuncAttributeMaxDynamicSharedMemorySize, DYN);

    // launch 0: all weight prepack + fused bias
    {
        const int total = 512*256 + 512*640 + 384*128 + 256*128 + 4*256*1152 + 384;
        prepack_all_k<<<(total + 255) / 256, 256>>>(
            cv1_w, cv2_w, vproj_w, off_w, aw_w, vproj_b, off_b, aw_b, out_w,
            mc0, mc1, mc2, mc3,
            wcv1_h, wcv1_l, wcv2_h, wcv2_l, wpj_h, wpj_l, wop_h, wop_l,
            wc_h, wc_l, biasc);
    }
    // launch 1: input prepack
    prepack_x_k<<<dim3(128, 8, NB), dim3(32, 8)>>>(x, xp_h, xp_l);

    // launch 2: cv1 -> cat [a|b] (pairs 0..255), SiLU
    mm_hmma<false,0,true,false><<<dim3(32, 4, NB), 256, DYN>>>(
        xp_h, xp_l, 256, 0, wcv1_h, wcv1_l, 256, nullptr,
        nullptr, 0, 0, catp_h, catp_l, 640, 0, 512);

    // launches 3-6: bottleneck convs b -> b1 -> b2
    mm_hmma<true,0,true,false><<<dim3(32, 2, NB), 256, DYN>>>(
        catp_h, catp_l, 640, 128, wc_h + 0*256*1152, wc_l + 0*256*1152, 1152, nullptr,
        nullptr, 0, 0, s0p_h, s0p_l, 128, 0, 2304);
    mm_hmma<true,0,true,false><<<dim3(32, 2, NB), 256, DYN>>>(
        s0p_h, s0p_l, 128, 0, wc_h + 1*256*1152, wc_l + 1*256*1152, 1152, nullptr,
        nullptr, 0, 0, catp_h, catp_l, 640, 256, 2304);
    mm_hmma<true,0,true,false><<<dim3(32, 2, NB), 256, DYN>>>(
        catp_h, catp_l, 640, 256, wc_h + 2*256*1152, wc_l + 2*256*1152, 1152, nullptr,
        nullptr, 0, 0, s0p_h, s0p_l, 128, 0, 2304);
    mm_hmma<true,0,true,false><<<dim3(32, 2, NB), 256, DYN>>>(
        s0p_h, s0p_l, 128, 0, wc_h + 3*256*1152, wc_l + 3*256*1152, 1152, nullptr,
        nullptr, 0, 0, catp_h, catp_l, 640, 384, 2304);

    // launch 7: fused projections (val|off|aw), fp32 out [row][384] + bias
    mm_hmma<false,1,false,true><<<dim3(32, 3, NB), 256, DYN>>>(
        catp_h, catp_l, 640, 384, wpj_h, wpj_l, 128, biasc,
        pj, 384, 4096L*384, nullptr, nullptr, 0, 0, 256);

    // launch 8: deformable sampling -> packed smp
    msda_sample_k<<<NB * HWN, 256>>>(pj, bbox, smpp_h, smpp_l);

    // launch 9: output projection -> cat attn section (pairs 512..639)
    mm_hmma<false,0,false,true><<<dim3(32, 2, NB), 256, DYN>>>(
        smpp_h, smpp_l, 128, 0, wop_h, wop_l, 128, out_b,
        nullptr, 0, 0, catp_h, catp_l, 640, 512, 256);

    // launch 10: cv2 K=1280, SiLU, channel-major fp32 out (coalesced via smem)
    mm_hmma<false,2,true,false><<<dim3(32, 4, NB), 256, DYN>>>(
        catp_h, catp_l, 640, 0, wcv2_h, wcv2_l, 640, nullptr,
        out, 4096, 512L*4096, nullptr, nullptr, 0, 0, 1280);
}